// round 14
// baseline (speedup 1.0000x reference)
#include <cuda_runtime.h>
#include <cuda_bf16.h>
#include <cuda_fp16.h>
#include <math.h>

#define NN 100000
#define EE 1600000
#define DIN 7
#define GG 64
#define CAP 96
#define HP 72          // half pitch for mma smem tiles (144B, conflict-free ldmatrix)
#define FULLMASK 0xffffffffu

// ---------------- scratch (device globals; no allocation allowed) -------------
__device__ uint4  g_xsh[NN + 1];        // x*dis as 8 fp16 (7 real + 0 pad); row NN = 0
__device__ float4 g_pre[NN * 2];        // pre1 = sum_src xs[src] + xs[self] (fp32)
__device__ uint2  g_u2h[(NN + 1) * 16]; // (hidden1 @ [W2|W3]) * dis (fp16); row NN = 0
__device__ int    g_slot[NN * CAP];     // per-dst src lists (padded to mult of 32)
__device__ int    g_cnt[NN];            // in-degree
__device__ float  g_pool[GG * 8];

__device__ __forceinline__ unsigned int sptr(const void* p) {
    return (unsigned int)__cvta_generic_to_shared(p);
}

// ---------------- CSR fill: 4 edges/thread, per-warp dtype detect -------------
__global__ void __launch_bounds__(256) fill_kernel(const char* __restrict__ ei) {
    int lane = threadIdx.x & 31;
    int probe = ((const int*)ei)[2 * lane + 1];
    bool is64 = (__ballot_sync(FULLMASK, probe != 0) == 0u);
    int t = blockIdx.x * 256 + threadIdx.x;
    if (t >= EE / 4) return;
    int s[4], d[4];
    if (is64) {
        const longlong2* sp = (const longlong2*)ei;
        const longlong2* dp = (const longlong2*)(ei + 8LL * EE);
        longlong2 a = sp[2 * t], b = sp[2 * t + 1];
        longlong2 c = dp[2 * t], e = dp[2 * t + 1];
        s[0] = (int)a.x; s[1] = (int)a.y; s[2] = (int)b.x; s[3] = (int)b.y;
        d[0] = (int)c.x; d[1] = (int)c.y; d[2] = (int)e.x; d[3] = (int)e.y;
    } else {
        int4 a = ((const int4*)ei)[t];
        int4 c = ((const int4*)(ei + 4LL * EE))[t];
        s[0] = a.x; s[1] = a.y; s[2] = a.z; s[3] = a.w;
        d[0] = c.x; d[1] = c.y; d[2] = c.z; d[3] = c.w;
    }
#pragma unroll
    for (int j = 0; j < 4; j++) {
        int pos = atomicAdd(&g_cnt[d[j]], 1);
        if (pos < CAP) g_slot[d[j] * CAP + pos] = s[j];
    }
}

// ---------------- xs = fp16[x*dis, 0]; pad slots to mult-32; zero dummies -----
__global__ void __launch_bounds__(256) xs_kernel(const float* __restrict__ x) {
    int n = blockIdx.x * 256 + threadIdx.x;
    if (n > NN) return;
    if (n == NN) {
        g_xsh[NN] = make_uint4(0u, 0u, 0u, 0u);
        uint2 z = make_uint2(0u, 0u);
#pragma unroll
        for (int i = 0; i < 16; i++) g_u2h[NN * 16 + i] = z;
        return;
    }
    int craw = g_cnt[n];
    float dv = rsqrtf((float)craw + 1.0f);
    const float* xr = x + n * DIN;
    __half2 h0 = __floats2half2_rn(xr[0] * dv, xr[1] * dv);
    __half2 h1 = __floats2half2_rn(xr[2] * dv, xr[3] * dv);
    __half2 h2 = __floats2half2_rn(xr[4] * dv, xr[5] * dv);
    __half2 h3 = __floats2half2_rn(xr[6] * dv, 0.f);
    uint4 v;
    v.x = *(unsigned int*)&h0;
    v.y = *(unsigned int*)&h1;
    v.z = *(unsigned int*)&h2;
    v.w = *(unsigned int*)&h3;
    g_xsh[n] = v;
    int c = min(craw, CAP);
    int cp = min((c + 31) & ~31, CAP);
    int k = c;
    int c4 = min((c + 3) & ~3, cp);
    for (; k < c4; k++) g_slot[n * CAP + k] = NN;
    int4 nn4 = make_int4(NN, NN, NN, NN);
    for (; k < cp; k += 4) *(int4*)&g_slot[n * CAP + k] = nn4;
}

// ---------------- gather-1: pre1 = sum_src xs[src] + xs[self] -----------------
// 8 lanes per node; int4 index prefetch -> 4 independent LDG.128 per lane.
__global__ void __launch_bounds__(256) gather1_kernel() {
    int tid = threadIdx.x, warp = tid >> 5, lane = tid & 31;
    int grp = lane >> 3, el = lane & 7;
    int node = blockIdx.x * 32 + warp * 4 + grp;   // NN % 32 == 0

    int craw = g_cnt[node];
    int c = min(craw, CAP);
    int cntp = min((c + 31) & ~31, CAP);
    const int* sl = &g_slot[node * CAP];

    float4 a0 = make_float4(0.f, 0.f, 0.f, 0.f);
    float4 a1 = make_float4(0.f, 0.f, 0.f, 0.f);
#define ACC8(v) { float2 q0 = __half22float2(*(__half2*)&(v).x); \
                  float2 q1 = __half22float2(*(__half2*)&(v).y); \
                  float2 q2 = __half22float2(*(__half2*)&(v).z); \
                  float2 q3 = __half22float2(*(__half2*)&(v).w); \
                  a0.x += q0.x; a0.y += q0.y; a0.z += q1.x; a0.w += q1.y; \
                  a1.x += q2.x; a1.y += q2.y; a1.z += q3.x; a1.w += q3.y; }
    for (int base = 0; base < cntp; base += 32) {
        int4 idx = ((const int4*)(sl + base))[el];    // 4 edges per lane
        uint4 v0 = g_xsh[idx.x];
        uint4 v1 = g_xsh[idx.y];
        uint4 v2 = g_xsh[idx.z];
        uint4 v3 = g_xsh[idx.w];
        ACC8(v0); ACC8(v1); ACC8(v2); ACC8(v3);
    }
#undef ACC8
#pragma unroll
    for (int off = 1; off <= 4; off <<= 1) {
        a0.x += __shfl_xor_sync(FULLMASK, a0.x, off);
        a0.y += __shfl_xor_sync(FULLMASK, a0.y, off);
        a0.z += __shfl_xor_sync(FULLMASK, a0.z, off);
        a0.w += __shfl_xor_sync(FULLMASK, a0.w, off);
        a1.x += __shfl_xor_sync(FULLMASK, a1.x, off);
        a1.y += __shfl_xor_sync(FULLMASK, a1.y, off);
        a1.z += __shfl_xor_sync(FULLMASK, a1.z, off);
        a1.w += __shfl_xor_sync(FULLMASK, a1.w, off);
    }
    if (el == 0) {
        uint4 sv = g_xsh[node];
        float2 p0 = __half22float2(*(__half2*)&sv.x);
        float2 p1 = __half22float2(*(__half2*)&sv.y);
        g_pre[2 * node] = make_float4(a0.x + p0.x, a0.y + p0.y, a0.z + p1.x, a0.w + p1.y);
    } else if (el == 4) {
        uint4 sv = g_xsh[node];
        float2 p2 = __half22float2(*(__half2*)&sv.z);
        float2 p3 = __half22float2(*(__half2*)&sv.w);
        g_pre[2 * node + 1] = make_float4(a1.x + p2.x, a1.y + p2.y, a1.z + p3.x, a1.w + p3.y);
    }
}

// ---------------- hidden1 (fp16 smem) + tensor-core GEMM -> u2 fp16 -----------
__global__ void __launch_bounds__(256) hidden_gemm_kernel(
    const float* __restrict__ W1, const float* __restrict__ b1,
    const float* __restrict__ W2, const float* __restrict__ W3) {
    __shared__ __half sh_h[64 * HP];    // hidden1, row-major [node][64]
    __shared__ __half sh_wt[64 * HP];   // Wc, row-major [k][64]
    __shared__ float sh_w1[DIN * 64];
    __shared__ float sh_b1[64];
    __shared__ float sh_pre[64 * 8];
    __shared__ float sh_dis[64];
    int tid = threadIdx.x;
    int nb = blockIdx.x * 64;

    for (int i = tid; i < 64 * 64; i += 256) {
        int k = i >> 6, j = i & 63;
        float wv = (j < 32) ? W2[k * 32 + j] : W3[k * 32 + (j - 32)];
        sh_wt[k * HP + j] = __float2half_rn(wv);
    }
    for (int i = tid; i < DIN * 64; i += 256) sh_w1[i] = W1[i];
    if (tid < 64) sh_b1[tid] = b1[tid];
    if (tid < 128) {
        int node = nb + (tid >> 1);
        float4 v = (node < NN) ? g_pre[2 * node + (tid & 1)]
                               : make_float4(0.f, 0.f, 0.f, 0.f);
        *(float4*)&sh_pre[tid * 4] = v;
    }
    if (tid < 64) {
        int node = nb + tid;
        sh_dis[tid] = (node < NN) ? rsqrtf((float)g_cnt[node] + 1.0f) : 0.f;
    }
    __syncthreads();

    // hidden1 = relu(dis * (pre1 @ W1) + b1) -> fp16 smem
    // thread = (node nl, 16-col segment js); vectorized LDS, 2 passes of 8 cols
    {
        int nl = tid >> 2;
        int js = (tid & 3) << 4;
        float4 p0 = *(const float4*)&sh_pre[nl * 8];
        float4 p1 = *(const float4*)&sh_pre[nl * 8 + 4];
        float pk[7] = {p0.x, p0.y, p0.z, p0.w, p1.x, p1.y, p1.z};
        float dvn = sh_dis[nl];
#pragma unroll
        for (int hseg = 0; hseg < 2; hseg++) {
            int jb = js + hseg * 8;
            float acc[8];
#pragma unroll
            for (int q = 0; q < 8; q++) acc[q] = 0.f;
#pragma unroll
            for (int k = 0; k < 7; k++) {
                float4 w0 = *(const float4*)&sh_w1[k * 64 + jb];
                float4 w1v = *(const float4*)&sh_w1[k * 64 + jb + 4];
                acc[0] += pk[k] * w0.x; acc[1] += pk[k] * w0.y;
                acc[2] += pk[k] * w0.z; acc[3] += pk[k] * w0.w;
                acc[4] += pk[k] * w1v.x; acc[5] += pk[k] * w1v.y;
                acc[6] += pk[k] * w1v.z; acc[7] += pk[k] * w1v.w;
            }
            float4 bb0 = *(const float4*)&sh_b1[jb];
            float4 bb1 = *(const float4*)&sh_b1[jb + 4];
            __half2 o0 = __floats2half2_rn(fmaxf(dvn * acc[0] + bb0.x, 0.f),
                                           fmaxf(dvn * acc[1] + bb0.y, 0.f));
            __half2 o1 = __floats2half2_rn(fmaxf(dvn * acc[2] + bb0.z, 0.f),
                                           fmaxf(dvn * acc[3] + bb0.w, 0.f));
            __half2 o2 = __floats2half2_rn(fmaxf(dvn * acc[4] + bb1.x, 0.f),
                                           fmaxf(dvn * acc[5] + bb1.y, 0.f));
            __half2 o3 = __floats2half2_rn(fmaxf(dvn * acc[6] + bb1.z, 0.f),
                                           fmaxf(dvn * acc[7] + bb1.w, 0.f));
            uint4 pack;
            pack.x = *(unsigned int*)&o0;
            pack.y = *(unsigned int*)&o1;
            pack.z = *(unsigned int*)&o2;
            pack.w = *(unsigned int*)&o3;
            *(uint4*)&sh_h[nl * HP + jb] = pack;   // 144B row pitch -> 16B aligned
        }
    }
    __syncthreads();

    // Tensor-core GEMM: warp w -> rows 16*(w/2), cols 32*(w%2)
    int warp = tid >> 5, lane = tid & 31;
    int wr = (warp >> 1) << 4, wc = (warp & 1) << 5;
    float d[4][4];
#pragma unroll
    for (int nt = 0; nt < 4; nt++)
#pragma unroll
        for (int q = 0; q < 4; q++) d[nt][q] = 0.f;

    int li8 = lane & 7, seg = lane >> 3;
#pragma unroll
    for (int k0 = 0; k0 < 64; k0 += 16) {
        unsigned int a0, a1, a2, a3;
        {
            unsigned int addr = sptr(&sh_h[(wr + li8 + (seg & 1) * 8) * HP + k0 + (seg >> 1) * 8]);
            asm volatile("ldmatrix.sync.aligned.m8n8.x4.shared.b16 {%0,%1,%2,%3}, [%4];"
                         : "=r"(a0), "=r"(a1), "=r"(a2), "=r"(a3) : "r"(addr));
        }
        unsigned int bfr[8];
#pragma unroll
        for (int hn = 0; hn < 2; hn++) {
            int n0 = wc + hn * 16;
            unsigned int addr = sptr(&sh_wt[(k0 + li8 + (seg & 1) * 8) * HP + n0 + (seg >> 1) * 8]);
            asm volatile("ldmatrix.sync.aligned.m8n8.x4.trans.shared.b16 {%0,%1,%2,%3}, [%4];"
                         : "=r"(bfr[4 * hn]), "=r"(bfr[4 * hn + 1]),
                           "=r"(bfr[4 * hn + 2]), "=r"(bfr[4 * hn + 3]) : "r"(addr));
        }
#pragma unroll
        for (int nt = 0; nt < 4; nt++) {
            asm volatile(
                "mma.sync.aligned.m16n8k16.row.col.f32.f16.f16.f32 "
                "{%0,%1,%2,%3}, {%4,%5,%6,%7}, {%8,%9}, {%0,%1,%2,%3};"
                : "+f"(d[nt][0]), "+f"(d[nt][1]), "+f"(d[nt][2]), "+f"(d[nt][3])
                : "r"(a0), "r"(a1), "r"(a2), "r"(a3),
                  "r"(bfr[2 * nt]), "r"(bfr[2 * nt + 1]));
        }
    }

    // Epilogue: scale by dis, pack fp16, store to g_u2h
    int r0 = wr + (lane >> 2);
    int cbase = wc + 2 * (lane & 3);
    unsigned int* u2 = (unsigned int*)g_u2h;
    int node0 = nb + r0, node1 = nb + r0 + 8;
    float dv0 = sh_dis[r0], dv1 = sh_dis[r0 + 8];
#pragma unroll
    for (int nt = 0; nt < 4; nt++) {
        int c = cbase + nt * 8;
        if (node0 < NN) {
            __half2 h = __floats2half2_rn(d[nt][0] * dv0, d[nt][1] * dv0);
            u2[(size_t)node0 * 32 + (c >> 1)] = *(unsigned int*)&h;
        }
        if (node1 < NN) {
            __half2 h = __floats2half2_rn(d[nt][2] * dv1, d[nt][3] * dv1);
            u2[(size_t)node1 * 32 + (c >> 1)] = *(unsigned int*)&h;
        }
    }
}

// ---------------- branchless padded fp16 gather core --------------------------
#define ACCV(v) { float2 _a = __half22float2(*(__half2*)&(v).x); \
                  float2 _b = __half22float2(*(__half2*)&(v).y); \
                  acc.x += _a.x; acc.y += _a.y; acc.z += _b.x; acc.w += _b.y; }

__device__ __forceinline__ float4 gatherp(const uint2* __restrict__ buf,
                                          const int* __restrict__ sl,
                                          int cntp, int half, int li) {
    float4 acc = make_float4(0.f, 0.f, 0.f, 0.f);
    int k = 0;
    for (; k + 16 <= cntp; k += 16) {
        int s0 = sl[k + half],      s1 = sl[k + half + 2];
        int s2 = sl[k + half + 4],  s3 = sl[k + half + 6];
        int s4 = sl[k + half + 8],  s5 = sl[k + half + 10];
        int s6 = sl[k + half + 12], s7 = sl[k + half + 14];
        uint2 v0 = buf[(size_t)s0 * 16 + li], v1 = buf[(size_t)s1 * 16 + li];
        uint2 v2 = buf[(size_t)s2 * 16 + li], v3 = buf[(size_t)s3 * 16 + li];
        uint2 v4 = buf[(size_t)s4 * 16 + li], v5 = buf[(size_t)s5 * 16 + li];
        uint2 v6 = buf[(size_t)s6 * 16 + li], v7 = buf[(size_t)s7 * 16 + li];
        ACCV(v0); ACCV(v1); ACCV(v2); ACCV(v3);
        ACCV(v4); ACCV(v5); ACCV(v6); ACCV(v7);
    }
    if (k < cntp) {
        int s0 = sl[k + half],     s1 = sl[k + half + 2];
        int s2 = sl[k + half + 4], s3 = sl[k + half + 6];
        uint2 v0 = buf[(size_t)s0 * 16 + li], v1 = buf[(size_t)s1 * 16 + li];
        uint2 v2 = buf[(size_t)s2 * 16 + li], v3 = buf[(size_t)s3 * 16 + li];
        ACCV(v0); ACCV(v1); ACCV(v2); ACCV(v3);
    }
    acc.x += __shfl_xor_sync(FULLMASK, acc.x, 16);
    acc.y += __shfl_xor_sync(FULLMASK, acc.y, 16);
    acc.z += __shfl_xor_sync(FULLMASK, acc.z, 16);
    acc.w += __shfl_xor_sync(FULLMASK, acc.w, 16);
    return acc;
}

// ---------------- fused gather-2 + mu/logvar/z (warp per node) ----------------
__global__ void __launch_bounds__(256) gather2_final_kernel(
    const float* __restrict__ b2, const float* __restrict__ b3,
    const float* __restrict__ eps, float* __restrict__ out) {
    int tid = threadIdx.x, warp = tid >> 5, lane = tid & 31;
    int half = lane >> 4, li = lane & 15;
    int node = blockIdx.x * 8 + warp;

    int craw = g_cnt[node];
    int c = min(craw, CAP);
    int cntp = min((c + 7) & ~7, CAP);
    const int* sl = &g_slot[node * CAP];
    float4 acc = gatherp(g_u2h, sl, cntp, half, li);

    float val[4] = {0.f, 0.f, 0.f, 0.f};
    if (half == 0) {
        uint2 sv = g_u2h[(size_t)node * 16 + li];
        float2 s0 = __half22float2(*(__half2*)&sv.x);
        float2 s1 = __half22float2(*(__half2*)&sv.y);
        float dv = rsqrtf((float)craw + 1.0f);
        int c0 = li * 4;
        const float* bsrc = (c0 < 32) ? &b2[c0] : &b3[c0 - 32];
        float4 bb = *(const float4*)bsrc;
        val[0] = fmaxf((acc.x + s0.x) * dv + bb.x, 0.f);
        val[1] = fmaxf((acc.y + s0.y) * dv + bb.y, 0.f);
        val[2] = fmaxf((acc.z + s1.x) * dv + bb.z, 0.f);
        val[3] = fmaxf((acc.w + s1.y) * dv + bb.w, 0.f);
    }
    float lv0 = __shfl_down_sync(FULLMASK, val[0], 8);
    float lv1 = __shfl_down_sync(FULLMASK, val[1], 8);
    float lv2 = __shfl_down_sync(FULLMASK, val[2], 8);
    float lv3 = __shfl_down_sync(FULLMASK, val[3], 8);

    const int NZ = NN * 32;
    const int NP = GG * DIN;
    if (lane < 8) {
        int t = node * 32 + lane * 4;
        float4 ev = *(const float4*)&eps[t];
        float4 z;
        z.x = ev.x * __expf(lv0) + val[0];
        z.y = ev.y * __expf(lv1) + val[1];
        z.z = ev.z * __expf(lv2) + val[2];
        z.w = ev.w * __expf(lv3) + val[3];
        *(float4*)&out[t] = z;
        *(float4*)&out[NZ + NP + t] = make_float4(val[0], val[1], val[2], val[3]);
    } else if (lane < 16) {
        int t = node * 32 + (lane - 8) * 4;
        *(float4*)&out[2 * NZ + NP + t] = make_float4(val[0], val[1], val[2], val[3]);
    }
}

// ---------------- pooling: warp-uniform fast path -----------------------------
__global__ void __launch_bounds__(256) pool_kernel(const float* __restrict__ x,
                                                   const char* __restrict__ batch,
                                                   const char* __restrict__ ei) {
    int lane = threadIdx.x & 31;
    int probe = ((const int*)ei)[2 * lane + 1];
    bool is64 = (__ballot_sync(FULLMASK, probe != 0) == 0u);
    int gw = (blockIdx.x * 256 + threadIdx.x) >> 5;
    int nw = (gridDim.x * 256) >> 5;
    for (int base = gw * 32; base < NN; base += nw * 32) {  // NN % 32 == 0
        int n = base + lane;
        int b = is64 ? (int)((const long long*)batch)[n] : ((const int*)batch)[n];
        float xv[DIN];
#pragma unroll
        for (int k = 0; k < DIN; k++) xv[k] = x[n * DIN + k];
        int b0 = __shfl_sync(FULLMASK, b, 0);
        if (__all_sync(FULLMASK, b == b0)) {
#pragma unroll
            for (int k = 0; k < DIN; k++)
#pragma unroll
                for (int o = 16; o > 0; o >>= 1)
                    xv[k] += __shfl_xor_sync(FULLMASK, xv[k], o);
            if (lane == 0) {
#pragma unroll
                for (int k = 0; k < DIN; k++) atomicAdd(&g_pool[b0 * 8 + k], xv[k]);
                atomicAdd(&g_pool[b0 * 8 + 7], 32.0f);
            }
        } else {
#pragma unroll
            for (int k = 0; k < DIN; k++) atomicAdd(&g_pool[b * 8 + k], xv[k]);
            atomicAdd(&g_pool[b * 8 + 7], 1.0f);
        }
    }
}

__global__ void poolfin_kernel(float* __restrict__ out) {
    int t = blockIdx.x * blockDim.x + threadIdx.x;
    if (t >= GG * DIN) return;
    int g = t / DIN, k = t % DIN;
    float cnt = g_pool[g * 8 + 7];
    out[NN * 32 + g * DIN + k] = g_pool[g * 8 + k] / fmaxf(cnt, 1.0f);
}

// ---------------- launch -----------------------------------------------------
extern "C" void kernel_launch(void* const* d_in, const int* in_sizes, int n_in,
                              void* d_out, int out_size) {
    const float* x   = (const float*)d_in[0];
    const char*  ei  = (const char*)d_in[1];
    const char*  bat = (const char*)d_in[2];
    const float* W1  = (const float*)d_in[3];
    const float* b1  = (const float*)d_in[4];
    const float* W2  = (const float*)d_in[5];
    const float* b2  = (const float*)d_in[6];
    const float* W3  = (const float*)d_in[7];
    const float* b3  = (const float*)d_in[8];
    const float* eps = (const float*)d_in[9];
    float* out = (float*)d_out;

    void *p_cnt, *p_pool;
    cudaGetSymbolAddress(&p_cnt, g_cnt);
    cudaGetSymbolAddress(&p_pool, g_pool);

    cudaMemsetAsync(p_cnt, 0, NN * sizeof(int), 0);
    cudaMemsetAsync(p_pool, 0, GG * 8 * sizeof(float), 0);

    fill_kernel<<<(EE / 4 + 255) / 256, 256>>>(ei);
    xs_kernel<<<(NN + 1 + 255) / 256, 256>>>(x);
    gather1_kernel<<<NN / 32, 256>>>();
    hidden_gemm_kernel<<<(NN + 63) / 64, 256>>>(W1, b1, W2, W3);
    gather2_final_kernel<<<NN / 8, 256>>>(b2, b3, eps, out);

    pool_kernel<<<128, 256>>>(x, bat, ei);
    poolfin_kernel<<<1, 512>>>(out);
}

// round 15
// speedup vs baseline: 1.0735x; 1.0735x over previous
#include <cuda_runtime.h>
#include <cuda_bf16.h>
#include <cuda_fp16.h>
#include <math.h>

#define NN 100000
#define EE 1600000
#define DIN 7
#define GG 64
#define CAP 96
#define HP 72          // half pitch for mma smem tiles (144B, conflict-free ldmatrix)
#define FULLMASK 0xffffffffu

// ---------------- scratch (device globals; no allocation allowed) -------------
__device__ uint4  g_xsh[NN + 1];        // x*dis as 8 fp16 (7 real + 0 pad); row NN = 0
__device__ float4 g_pre[NN * 2];        // pre1 = sum_src xs[src] + xs[self] (fp32)
__device__ uint2  g_u2h[(NN + 1) * 16]; // (hidden1 @ [W2|W3]) * dis (fp16); row NN = 0
__device__ int    g_slot[NN * CAP];     // per-dst src lists (padded to mult of 8)
__device__ int    g_cnt[NN];            // in-degree
__device__ float  g_pool[GG * 8];

__device__ __forceinline__ unsigned int sptr(const void* p) {
    return (unsigned int)__cvta_generic_to_shared(p);
}

// ---------------- CSR fill: 4 edges/thread, per-warp dtype detect -------------
__global__ void __launch_bounds__(256) fill_kernel(const char* __restrict__ ei) {
    int lane = threadIdx.x & 31;
    int probe = ((const int*)ei)[2 * lane + 1];
    bool is64 = (__ballot_sync(FULLMASK, probe != 0) == 0u);
    int t = blockIdx.x * 256 + threadIdx.x;
    if (t >= EE / 4) return;
    int s[4], d[4];
    if (is64) {
        const longlong2* sp = (const longlong2*)ei;
        const longlong2* dp = (const longlong2*)(ei + 8LL * EE);
        longlong2 a = sp[2 * t], b = sp[2 * t + 1];
        longlong2 c = dp[2 * t], e = dp[2 * t + 1];
        s[0] = (int)a.x; s[1] = (int)a.y; s[2] = (int)b.x; s[3] = (int)b.y;
        d[0] = (int)c.x; d[1] = (int)c.y; d[2] = (int)e.x; d[3] = (int)e.y;
    } else {
        int4 a = ((const int4*)ei)[t];
        int4 c = ((const int4*)(ei + 4LL * EE))[t];
        s[0] = a.x; s[1] = a.y; s[2] = a.z; s[3] = a.w;
        d[0] = c.x; d[1] = c.y; d[2] = c.z; d[3] = c.w;
    }
#pragma unroll
    for (int j = 0; j < 4; j++) {
        int pos = atomicAdd(&g_cnt[d[j]], 1);
        if (pos < CAP) g_slot[d[j] * CAP + pos] = s[j];
    }
}

// ---------------- xs = fp16[x*dis, 0] ; pad slots ; zero dummy rows -----------
__global__ void __launch_bounds__(256) xs_kernel(const float* __restrict__ x) {
    int n = blockIdx.x * 256 + threadIdx.x;
    if (n > NN) return;
    if (n == NN) {
        g_xsh[NN] = make_uint4(0u, 0u, 0u, 0u);
        uint2 z = make_uint2(0u, 0u);
#pragma unroll
        for (int i = 0; i < 16; i++) g_u2h[NN * 16 + i] = z;
        return;
    }
    int craw = g_cnt[n];
    float dv = rsqrtf((float)craw + 1.0f);
    const float* xr = x + n * DIN;
    __half2 h0 = __floats2half2_rn(xr[0] * dv, xr[1] * dv);
    __half2 h1 = __floats2half2_rn(xr[2] * dv, xr[3] * dv);
    __half2 h2 = __floats2half2_rn(xr[4] * dv, xr[5] * dv);
    __half2 h3 = __floats2half2_rn(xr[6] * dv, 0.f);
    uint4 v;
    v.x = *(unsigned int*)&h0;
    v.y = *(unsigned int*)&h1;
    v.z = *(unsigned int*)&h2;
    v.w = *(unsigned int*)&h3;
    g_xsh[n] = v;
    int c = min(craw, CAP);
    int cp = min((c + 7) & ~7, CAP);
    for (int k = c; k < cp; k++) g_slot[n * CAP + k] = NN;
}

// ---------------- gather-1: pre1 = sum_src xs[src] + xs[self] -----------------
// 8 lanes per node; ONE LDG.128 per edge (fp16 xs); fp32 accumulate.
__global__ void __launch_bounds__(256) gather1_kernel() {
    int tid = threadIdx.x, warp = tid >> 5, lane = tid & 31;
    int grp = lane >> 3, el = lane & 7;
    int node = blockIdx.x * 32 + warp * 4 + grp;   // NN % 32 == 0

    int craw = g_cnt[node];
    int c = min(craw, CAP);
    int cntp = min((c + 7) & ~7, CAP);
    const int* sl = &g_slot[node * CAP];

    float4 a0 = make_float4(0.f, 0.f, 0.f, 0.f);
    float4 a1 = make_float4(0.f, 0.f, 0.f, 0.f);
    for (int base = 0; base < cntp; base += 8) {
        uint4 v = g_xsh[sl[base + el]];        // padded with NN (zero row, L1-hit)
        float2 p0 = __half22float2(*(__half2*)&v.x);
        float2 p1 = __half22float2(*(__half2*)&v.y);
        float2 p2 = __half22float2(*(__half2*)&v.z);
        float2 p3 = __half22float2(*(__half2*)&v.w);
        a0.x += p0.x; a0.y += p0.y; a0.z += p1.x; a0.w += p1.y;
        a1.x += p2.x; a1.y += p2.y; a1.z += p3.x; a1.w += p3.y;
    }
#pragma unroll
    for (int off = 1; off <= 4; off <<= 1) {
        a0.x += __shfl_xor_sync(FULLMASK, a0.x, off);
        a0.y += __shfl_xor_sync(FULLMASK, a0.y, off);
        a0.z += __shfl_xor_sync(FULLMASK, a0.z, off);
        a0.w += __shfl_xor_sync(FULLMASK, a0.w, off);
        a1.x += __shfl_xor_sync(FULLMASK, a1.x, off);
        a1.y += __shfl_xor_sync(FULLMASK, a1.y, off);
        a1.z += __shfl_xor_sync(FULLMASK, a1.z, off);
        a1.w += __shfl_xor_sync(FULLMASK, a1.w, off);
    }
    if (el == 0) {
        uint4 sv = g_xsh[node];
        float2 p0 = __half22float2(*(__half2*)&sv.x);
        float2 p1 = __half22float2(*(__half2*)&sv.y);
        g_pre[2 * node] = make_float4(a0.x + p0.x, a0.y + p0.y, a0.z + p1.x, a0.w + p1.y);
    } else if (el == 4) {
        uint4 sv = g_xsh[node];
        float2 p2 = __half22float2(*(__half2*)&sv.z);
        float2 p3 = __half22float2(*(__half2*)&sv.w);
        g_pre[2 * node + 1] = make_float4(a1.x + p2.x, a1.y + p2.y, a1.z + p3.x, a1.w + p3.y);
    }
}

// ---------------- hidden1 (fp16 smem) + tensor-core GEMM -> u2 fp16 -----------
// R13 structure; pre/cnt LDGs hoisted ahead of weight staging; float2 Wc stage.
__global__ void __launch_bounds__(256) hidden_gemm_kernel(
    const float* __restrict__ W1, const float* __restrict__ b1,
    const float* __restrict__ W2, const float* __restrict__ W3) {
    __shared__ __half sh_h[64 * HP];    // hidden1, row-major [node][64]
    __shared__ __half sh_wt[64 * HP];   // Wc, row-major [k][64]
    __shared__ float sh_w1[DIN * 64];
    __shared__ float sh_b1[64];
    __shared__ float sh_pre[64 * 8];
    __shared__ float sh_dis[64];
    int tid = threadIdx.x;
    int nb = blockIdx.x * 64;

    // ---- issue long-latency global loads FIRST (overlap with staging) ----
    float4 prev = make_float4(0.f, 0.f, 0.f, 0.f);
    if (tid < 128) {
        int node = nb + (tid >> 1);
        if (node < NN) prev = g_pre[2 * node + (tid & 1)];
    }
    float disv = 0.f;
    if (tid < 64) {
        int node = nb + tid;
        if (node < NN) disv = rsqrtf((float)g_cnt[node] + 1.0f);
    }

    // ---- stage weights: Wc as float2->half2 (8 iters), W1, b1 ----
    for (int i = tid; i < 2048; i += 256) {          // 2048 half2 pairs
        int k = i >> 5, jp = i & 31;                 // j = 2*jp
        float2 wv = (jp < 16) ? *(const float2*)&W2[k * 32 + 2 * jp]
                              : *(const float2*)&W3[k * 32 + (2 * jp - 32)];
        __half2 h = __floats2half2_rn(wv.x, wv.y);
        *(__half2*)&sh_wt[k * HP + 2 * jp] = h;
    }
    for (int i = tid; i < DIN * 64; i += 256) sh_w1[i] = W1[i];
    if (tid < 64) sh_b1[tid] = b1[tid];
    if (tid < 128) *(float4*)&sh_pre[tid * 4] = prev;
    if (tid < 64) sh_dis[tid] = disv;
    __syncthreads();

    // hidden1 = relu(dis * (pre1 @ W1) + b1) -> fp16 smem
    for (int i = tid; i < 64 * 64; i += 256) {
        int nl = i >> 6, j = i & 63;
        float acc = 0.f;
#pragma unroll
        for (int k = 0; k < DIN; k++) acc += sh_pre[nl * 8 + k] * sh_w1[k * 64 + j];
        sh_h[nl * HP + j] = __float2half_rn(fmaxf(sh_dis[nl] * acc + sh_b1[j], 0.f));
    }
    __syncthreads();

    // Tensor-core GEMM: warp w -> rows 16*(w/2), cols 32*(w%2)
    int warp = tid >> 5, lane = tid & 31;
    int wr = (warp >> 1) << 4, wc = (warp & 1) << 5;
    float d[4][4];
#pragma unroll
    for (int nt = 0; nt < 4; nt++)
#pragma unroll
        for (int q = 0; q < 4; q++) d[nt][q] = 0.f;

    int li8 = lane & 7, seg = lane >> 3;
#pragma unroll
    for (int k0 = 0; k0 < 64; k0 += 16) {
        unsigned int a0, a1, a2, a3;
        {
            unsigned int addr = sptr(&sh_h[(wr + li8 + (seg & 1) * 8) * HP + k0 + (seg >> 1) * 8]);
            asm volatile("ldmatrix.sync.aligned.m8n8.x4.shared.b16 {%0,%1,%2,%3}, [%4];"
                         : "=r"(a0), "=r"(a1), "=r"(a2), "=r"(a3) : "r"(addr));
        }
        unsigned int bfr[8];
#pragma unroll
        for (int hn = 0; hn < 2; hn++) {
            int n0 = wc + hn * 16;
            unsigned int addr = sptr(&sh_wt[(k0 + li8 + (seg & 1) * 8) * HP + n0 + (seg >> 1) * 8]);
            asm volatile("ldmatrix.sync.aligned.m8n8.x4.trans.shared.b16 {%0,%1,%2,%3}, [%4];"
                         : "=r"(bfr[4 * hn]), "=r"(bfr[4 * hn + 1]),
                           "=r"(bfr[4 * hn + 2]), "=r"(bfr[4 * hn + 3]) : "r"(addr));
        }
#pragma unroll
        for (int nt = 0; nt < 4; nt++) {
            asm volatile(
                "mma.sync.aligned.m16n8k16.row.col.f32.f16.f16.f32 "
                "{%0,%1,%2,%3}, {%4,%5,%6,%7}, {%8,%9}, {%0,%1,%2,%3};"
                : "+f"(d[nt][0]), "+f"(d[nt][1]), "+f"(d[nt][2]), "+f"(d[nt][3])
                : "r"(a0), "r"(a1), "r"(a2), "r"(a3),
                  "r"(bfr[2 * nt]), "r"(bfr[2 * nt + 1]));
        }
    }

    // Epilogue: scale by dis, pack fp16, store to g_u2h
    int r0 = wr + (lane >> 2);
    int cbase = wc + 2 * (lane & 3);
    unsigned int* u2 = (unsigned int*)g_u2h;
    int node0 = nb + r0, node1 = nb + r0 + 8;
    float dv0 = sh_dis[r0], dv1 = sh_dis[r0 + 8];
#pragma unroll
    for (int nt = 0; nt < 4; nt++) {
        int c = cbase + nt * 8;
        if (node0 < NN) {
            __half2 h = __floats2half2_rn(d[nt][0] * dv0, d[nt][1] * dv0);
            u2[(size_t)node0 * 32 + (c >> 1)] = *(unsigned int*)&h;
        }
        if (node1 < NN) {
            __half2 h = __floats2half2_rn(d[nt][2] * dv1, d[nt][3] * dv1);
            u2[(size_t)node1 * 32 + (c >> 1)] = *(unsigned int*)&h;
        }
    }
}

// ---------------- branchless padded fp16 gather core --------------------------
#define ACCV(v) { float2 _a = __half22float2(*(__half2*)&(v).x); \
                  float2 _b = __half22float2(*(__half2*)&(v).y); \
                  acc.x += _a.x; acc.y += _a.y; acc.z += _b.x; acc.w += _b.y; }

__device__ __forceinline__ float4 gatherp(const uint2* __restrict__ buf,
                                          const int* __restrict__ sl,
                                          int cntp, int half, int li) {
    float4 acc = make_float4(0.f, 0.f, 0.f, 0.f);
    int k = 0;
    for (; k + 16 <= cntp; k += 16) {
        int s0 = sl[k + half],      s1 = sl[k + half + 2];
        int s2 = sl[k + half + 4],  s3 = sl[k + half + 6];
        int s4 = sl[k + half + 8],  s5 = sl[k + half + 10];
        int s6 = sl[k + half + 12], s7 = sl[k + half + 14];
        uint2 v0 = buf[(size_t)s0 * 16 + li], v1 = buf[(size_t)s1 * 16 + li];
        uint2 v2 = buf[(size_t)s2 * 16 + li], v3 = buf[(size_t)s3 * 16 + li];
        uint2 v4 = buf[(size_t)s4 * 16 + li], v5 = buf[(size_t)s5 * 16 + li];
        uint2 v6 = buf[(size_t)s6 * 16 + li], v7 = buf[(size_t)s7 * 16 + li];
        ACCV(v0); ACCV(v1); ACCV(v2); ACCV(v3);
        ACCV(v4); ACCV(v5); ACCV(v6); ACCV(v7);
    }
    if (k < cntp) {
        int s0 = sl[k + half],     s1 = sl[k + half + 2];
        int s2 = sl[k + half + 4], s3 = sl[k + half + 6];
        uint2 v0 = buf[(size_t)s0 * 16 + li], v1 = buf[(size_t)s1 * 16 + li];
        uint2 v2 = buf[(size_t)s2 * 16 + li], v3 = buf[(size_t)s3 * 16 + li];
        ACCV(v0); ACCV(v1); ACCV(v2); ACCV(v3);
    }
    acc.x += __shfl_xor_sync(FULLMASK, acc.x, 16);
    acc.y += __shfl_xor_sync(FULLMASK, acc.y, 16);
    acc.z += __shfl_xor_sync(FULLMASK, acc.z, 16);
    acc.w += __shfl_xor_sync(FULLMASK, acc.w, 16);
    return acc;
}

// ---------------- fused gather-2 + mu/logvar/z (warp per node) ----------------
__global__ void __launch_bounds__(256) gather2_final_kernel(
    const float* __restrict__ b2, const float* __restrict__ b3,
    const float* __restrict__ eps, float* __restrict__ out) {
    int tid = threadIdx.x, warp = tid >> 5, lane = tid & 31;
    int half = lane >> 4, li = lane & 15;
    int node = blockIdx.x * 8 + warp;

    int craw = g_cnt[node];
    int c = min(craw, CAP);
    int cntp = min((c + 7) & ~7, CAP);
    const int* sl = &g_slot[node * CAP];
    float4 acc = gatherp(g_u2h, sl, cntp, half, li);

    float val[4] = {0.f, 0.f, 0.f, 0.f};
    if (half == 0) {
        uint2 sv = g_u2h[(size_t)node * 16 + li];
        float2 s0 = __half22float2(*(__half2*)&sv.x);
        float2 s1 = __half22float2(*(__half2*)&sv.y);
        float dv = rsqrtf((float)craw + 1.0f);
        int c0 = li * 4;
        const float* bsrc = (c0 < 32) ? &b2[c0] : &b3[c0 - 32];
        float4 bb = *(const float4*)bsrc;
        val[0] = fmaxf((acc.x + s0.x) * dv + bb.x, 0.f);
        val[1] = fmaxf((acc.y + s0.y) * dv + bb.y, 0.f);
        val[2] = fmaxf((acc.z + s1.x) * dv + bb.z, 0.f);
        val[3] = fmaxf((acc.w + s1.y) * dv + bb.w, 0.f);
    }
    float lv0 = __shfl_down_sync(FULLMASK, val[0], 8);
    float lv1 = __shfl_down_sync(FULLMASK, val[1], 8);
    float lv2 = __shfl_down_sync(FULLMASK, val[2], 8);
    float lv3 = __shfl_down_sync(FULLMASK, val[3], 8);

    const int NZ = NN * 32;
    const int NP = GG * DIN;
    if (lane < 8) {
        int t = node * 32 + lane * 4;
        float4 ev = *(const float4*)&eps[t];
        float4 z;
        z.x = ev.x * __expf(lv0) + val[0];
        z.y = ev.y * __expf(lv1) + val[1];
        z.z = ev.z * __expf(lv2) + val[2];
        z.w = ev.w * __expf(lv3) + val[3];
        *(float4*)&out[t] = z;
        *(float4*)&out[NZ + NP + t] = make_float4(val[0], val[1], val[2], val[3]);
    } else if (lane < 16) {
        int t = node * 32 + (lane - 8) * 4;
        *(float4*)&out[2 * NZ + NP + t] = make_float4(val[0], val[1], val[2], val[3]);
    }
}

// ---------------- pooling: warp-uniform fast path -----------------------------
__global__ void __launch_bounds__(256) pool_kernel(const float* __restrict__ x,
                                                   const char* __restrict__ batch,
                                                   const char* __restrict__ ei) {
    int lane = threadIdx.x & 31;
    int probe = ((const int*)ei)[2 * lane + 1];
    bool is64 = (__ballot_sync(FULLMASK, probe != 0) == 0u);
    int gw = (blockIdx.x * 256 + threadIdx.x) >> 5;
    int nw = (gridDim.x * 256) >> 5;
    for (int base = gw * 32; base < NN; base += nw * 32) {  // NN % 32 == 0
        int n = base + lane;
        int b = is64 ? (int)((const long long*)batch)[n] : ((const int*)batch)[n];
        float xv[DIN];
#pragma unroll
        for (int k = 0; k < DIN; k++) xv[k] = x[n * DIN + k];
        int b0 = __shfl_sync(FULLMASK, b, 0);
        if (__all_sync(FULLMASK, b == b0)) {
#pragma unroll
            for (int k = 0; k < DIN; k++)
#pragma unroll
                for (int o = 16; o > 0; o >>= 1)
                    xv[k] += __shfl_xor_sync(FULLMASK, xv[k], o);
            if (lane == 0) {
#pragma unroll
                for (int k = 0; k < DIN; k++) atomicAdd(&g_pool[b0 * 8 + k], xv[k]);
                atomicAdd(&g_pool[b0 * 8 + 7], 32.0f);
            }
        } else {
#pragma unroll
            for (int k = 0; k < DIN; k++) atomicAdd(&g_pool[b * 8 + k], xv[k]);
            atomicAdd(&g_pool[b * 8 + 7], 1.0f);
        }
    }
}

__global__ void poolfin_kernel(float* __restrict__ out) {
    int t = blockIdx.x * blockDim.x + threadIdx.x;
    if (t >= GG * DIN) return;
    int g = t / DIN, k = t % DIN;
    float cnt = g_pool[g * 8 + 7];
    out[NN * 32 + g * DIN + k] = g_pool[g * 8 + k] / fmaxf(cnt, 1.0f);
}

// ---------------- launch -----------------------------------------------------
extern "C" void kernel_launch(void* const* d_in, const int* in_sizes, int n_in,
                              void* d_out, int out_size) {
    const float* x   = (const float*)d_in[0];
    const char*  ei  = (const char*)d_in[1];
    const char*  bat = (const char*)d_in[2];
    const float* W1  = (const float*)d_in[3];
    const float* b1  = (const float*)d_in[4];
    const float* W2  = (const float*)d_in[5];
    const float* b2  = (const float*)d_in[6];
    const float* W3  = (const float*)d_in[7];
    const float* b3  = (const float*)d_in[8];
    const float* eps = (const float*)d_in[9];
    float* out = (float*)d_out;

    void *p_cnt, *p_pool;
    cudaGetSymbolAddress(&p_cnt, g_cnt);
    cudaGetSymbolAddress(&p_pool, g_pool);

    cudaMemsetAsync(p_cnt, 0, NN * sizeof(int), 0);
    cudaMemsetAsync(p_pool, 0, GG * 8 * sizeof(float), 0);

    fill_kernel<<<(EE / 4 + 255) / 256, 256>>>(ei);
    xs_kernel<<<(NN + 1 + 255) / 256, 256>>>(x);
    gather1_kernel<<<NN / 32, 256>>>();
    hidden_gemm_kernel<<<(NN + 63) / 64, 256>>>(W1, b1, W2, W3);
    gather2_final_kernel<<<NN / 8, 256>>>(b2, b3, eps, out);

    pool_kernel<<<128, 256>>>(x, bat, ei);
    poolfin_kernel<<<1, 512>>>(out);
}

// round 16
// speedup vs baseline: 1.2240x; 1.1402x over previous
#include <cuda_runtime.h>
#include <cuda_bf16.h>
#include <cuda_fp16.h>
#include <math.h>

#define NN 100000
#define EE 1600000
#define DIN 7
#define GG 64
#define CAP 96
#define HP 72          // half pitch for mma smem tiles (144B, conflict-free ldmatrix)
#define FULLMASK 0xffffffffu

// ---------------- scratch (device globals; no allocation allowed) -------------
__device__ uint4  g_xsh[NN + 1];        // x*dis as 8 fp16 (7 real + 0 pad); row NN = 0
__device__ float4 g_pre[NN * 2];        // pre1 = sum_src xs[src] + xs[self] (fp32)
__device__ uint2  g_u2h[(NN + 1) * 16]; // (hidden1 @ [W2|W3]) * dis (fp16); row NN = 0
__device__ int    g_slot[NN * CAP];     // per-dst src lists (padded to mult of 8)
__device__ int    g_cnt[NN];            // in-degree
__device__ float  g_pool[GG * 8];

__device__ __forceinline__ unsigned int sptr(const void* p) {
    return (unsigned int)__cvta_generic_to_shared(p);
}

// ---------------- CSR fill: 4 edges/thread, per-warp dtype detect -------------
__global__ void __launch_bounds__(256) fill_kernel(const char* __restrict__ ei) {
    int lane = threadIdx.x & 31;
    int probe = ((const int*)ei)[2 * lane + 1];
    bool is64 = (__ballot_sync(FULLMASK, probe != 0) == 0u);
    int t = blockIdx.x * 256 + threadIdx.x;
    if (t >= EE / 4) return;
    int s[4], d[4];
    if (is64) {
        const longlong2* sp = (const longlong2*)ei;
        const longlong2* dp = (const longlong2*)(ei + 8LL * EE);
        longlong2 a = sp[2 * t], b = sp[2 * t + 1];
        longlong2 c = dp[2 * t], e = dp[2 * t + 1];
        s[0] = (int)a.x; s[1] = (int)a.y; s[2] = (int)b.x; s[3] = (int)b.y;
        d[0] = (int)c.x; d[1] = (int)c.y; d[2] = (int)e.x; d[3] = (int)e.y;
    } else {
        int4 a = ((const int4*)ei)[t];
        int4 c = ((const int4*)(ei + 4LL * EE))[t];
        s[0] = a.x; s[1] = a.y; s[2] = a.z; s[3] = a.w;
        d[0] = c.x; d[1] = c.y; d[2] = c.z; d[3] = c.w;
    }
#pragma unroll
    for (int j = 0; j < 4; j++) {
        int pos = atomicAdd(&g_cnt[d[j]], 1);
        if (pos < CAP) g_slot[d[j] * CAP + pos] = s[j];
    }
}

// ---------------- xs = fp16[x*dis, 0] ; pad slots ; zero dummy rows -----------
__global__ void __launch_bounds__(256) xs_kernel(const float* __restrict__ x) {
    int n = blockIdx.x * 256 + threadIdx.x;
    if (n > NN) return;
    if (n == NN) {
        g_xsh[NN] = make_uint4(0u, 0u, 0u, 0u);
        uint2 z = make_uint2(0u, 0u);
#pragma unroll
        for (int i = 0; i < 16; i++) g_u2h[NN * 16 + i] = z;
        return;
    }
    int craw = g_cnt[n];
    float dv = rsqrtf((float)craw + 1.0f);
    const float* xr = x + n * DIN;
    __half2 h0 = __floats2half2_rn(xr[0] * dv, xr[1] * dv);
    __half2 h1 = __floats2half2_rn(xr[2] * dv, xr[3] * dv);
    __half2 h2 = __floats2half2_rn(xr[4] * dv, xr[5] * dv);
    __half2 h3 = __floats2half2_rn(xr[6] * dv, 0.f);
    uint4 v;
    v.x = *(unsigned int*)&h0;
    v.y = *(unsigned int*)&h1;
    v.z = *(unsigned int*)&h2;
    v.w = *(unsigned int*)&h3;
    g_xsh[n] = v;
    int c = min(craw, CAP);
    int cp = min((c + 7) & ~7, CAP);
    for (int k = c; k < cp; k++) g_slot[n * CAP + k] = NN;
}

// ---------------- gather-1: pre1 = sum_src xs[src] + xs[self] -----------------
// 8 lanes per node; ONE LDG.128 per edge (fp16 xs); fp32 accumulate.
__global__ void __launch_bounds__(256) gather1_kernel() {
    int tid = threadIdx.x, warp = tid >> 5, lane = tid & 31;
    int grp = lane >> 3, el = lane & 7;
    int node = blockIdx.x * 32 + warp * 4 + grp;   // NN % 32 == 0

    int craw = g_cnt[node];
    int c = min(craw, CAP);
    int cntp = min((c + 7) & ~7, CAP);
    const int* sl = &g_slot[node * CAP];

    float4 a0 = make_float4(0.f, 0.f, 0.f, 0.f);
    float4 a1 = make_float4(0.f, 0.f, 0.f, 0.f);
    for (int base = 0; base < cntp; base += 8) {
        uint4 v = g_xsh[sl[base + el]];        // padded with NN (zero row, L1-hit)
        float2 p0 = __half22float2(*(__half2*)&v.x);
        float2 p1 = __half22float2(*(__half2*)&v.y);
        float2 p2 = __half22float2(*(__half2*)&v.z);
        float2 p3 = __half22float2(*(__half2*)&v.w);
        a0.x += p0.x; a0.y += p0.y; a0.z += p1.x; a0.w += p1.y;
        a1.x += p2.x; a1.y += p2.y; a1.z += p3.x; a1.w += p3.y;
    }
#pragma unroll
    for (int off = 1; off <= 4; off <<= 1) {
        a0.x += __shfl_xor_sync(FULLMASK, a0.x, off);
        a0.y += __shfl_xor_sync(FULLMASK, a0.y, off);
        a0.z += __shfl_xor_sync(FULLMASK, a0.z, off);
        a0.w += __shfl_xor_sync(FULLMASK, a0.w, off);
        a1.x += __shfl_xor_sync(FULLMASK, a1.x, off);
        a1.y += __shfl_xor_sync(FULLMASK, a1.y, off);
        a1.z += __shfl_xor_sync(FULLMASK, a1.z, off);
        a1.w += __shfl_xor_sync(FULLMASK, a1.w, off);
    }
    if (el == 0) {
        uint4 sv = g_xsh[node];
        float2 p0 = __half22float2(*(__half2*)&sv.x);
        float2 p1 = __half22float2(*(__half2*)&sv.y);
        g_pre[2 * node] = make_float4(a0.x + p0.x, a0.y + p0.y, a0.z + p1.x, a0.w + p1.y);
    } else if (el == 4) {
        uint4 sv = g_xsh[node];
        float2 p2 = __half22float2(*(__half2*)&sv.z);
        float2 p3 = __half22float2(*(__half2*)&sv.w);
        g_pre[2 * node + 1] = make_float4(a1.x + p2.x, a1.y + p2.y, a1.z + p3.x, a1.w + p3.y);
    }
}

// ---------------- fully MMA-chained hidden + GEMM -> u2 fp16 ------------------
// 64 nodes/block, ONE barrier, no sh_h/sh_pre. pre@W1 via m16n8k8, then
// D-frags relu/bias/dis -> A-frags for m16n8k16 against Wc.
__global__ void __launch_bounds__(256) hidden_gemm_kernel(
    const float* __restrict__ W1, const float* __restrict__ b1,
    const float* __restrict__ W2, const float* __restrict__ W3) {
    __shared__ __half sh_wt[64 * HP];        // Wc, row-major [k][64]
    __shared__ unsigned int sh_w1h[64 * 4];  // [n][m] = half2(W1[2m][n], W1[2m+1][n] or 0)
    __shared__ float sh_b1[64];
    int tid = threadIdx.x;
    int nb = blockIdx.x * 64;
    int warp = tid >> 5, lane = tid & 31;
    int wr = (warp >> 1) << 4, wc = (warp & 1) << 5;
    int gr = lane >> 2, m = lane & 3;
    int r1 = nb + wr + gr, r2 = r1 + 8;

    // ---- long-latency loads first (overlap with staging) ----
    float2 pA = make_float2(0.f, 0.f), pB = make_float2(0.f, 0.f);
    float dv0 = 0.f, dv1 = 0.f;
    if (r1 < NN) {
        pA = *(const float2*)&((const float*)g_pre)[r1 * 8 + 2 * m];
        dv0 = rsqrtf((float)g_cnt[r1] + 1.0f);
    }
    if (r2 < NN) {
        pB = *(const float2*)&((const float*)g_pre)[r2 * 8 + 2 * m];
        dv1 = rsqrtf((float)g_cnt[r2] + 1.0f);
    }

    // ---- stage Wc (float2 -> half2) ----
    for (int i = tid; i < 2048; i += 256) {          // 2048 half2 pairs
        int k = i >> 5, jp = i & 31;                 // j = 2*jp
        float2 wv = (jp < 16) ? *(const float2*)&W2[k * 32 + 2 * jp]
                              : *(const float2*)&W3[k * 32 + (2 * jp - 32)];
        __half2 h = __floats2half2_rn(wv.x, wv.y);
        *(__half2*)&sh_wt[k * HP + 2 * jp] = h;
    }
    // ---- stage packed W1 fragments: tid -> n=tid>>2, mm=tid&3 ----
    {
        int n = tid >> 2, mm = tid & 3;
        float lo = W1[2 * mm * 64 + n];
        float hi = (mm == 3) ? 0.f : W1[(2 * mm + 1) * 64 + n];
        __half2 h = __floats2half2_rn(lo, hi);
        sh_w1h[tid] = *(unsigned int*)&h;
    }
    if (tid < 64) sh_b1[tid] = b1[tid];
    __syncthreads();

    // ---- MMA1: hidden[16 x 64] = pre[16 x 8] @ W1[8 x 64] (8 n-tiles) ----
    __half2 a0h = __floats2half2_rn(pA.x, pA.y);
    __half2 a1h = __floats2half2_rn(pB.x, pB.y);
    unsigned int A0 = *(unsigned int*)&a0h;
    unsigned int A1 = *(unsigned int*)&a1h;

    float d1[8][4];
#pragma unroll
    for (int nt = 0; nt < 8; nt++) {
        d1[nt][0] = 0.f; d1[nt][1] = 0.f; d1[nt][2] = 0.f; d1[nt][3] = 0.f;
        unsigned int bw = sh_w1h[lane + 32 * nt];
        asm volatile(
            "mma.sync.aligned.m16n8k8.row.col.f32.f16.f16.f32 "
            "{%0,%1,%2,%3}, {%4,%5}, {%6}, {%0,%1,%2,%3};"
            : "+f"(d1[nt][0]), "+f"(d1[nt][1]), "+f"(d1[nt][2]), "+f"(d1[nt][3])
            : "r"(A0), "r"(A1), "r"(bw));
    }

    // ---- epilogue-1: relu(dis*d + b1) -> A-frags for MMA2 ----
    unsigned int A2[4][4];
#pragma unroll
    for (int nt = 0; nt < 8; nt++) {
        float2 bb = *(const float2*)&sh_b1[8 * nt + 2 * m];
        float h0 = fmaxf(dv0 * d1[nt][0] + bb.x, 0.f);
        float h1 = fmaxf(dv0 * d1[nt][1] + bb.y, 0.f);
        float h2 = fmaxf(dv1 * d1[nt][2] + bb.x, 0.f);
        float h3 = fmaxf(dv1 * d1[nt][3] + bb.y, 0.f);
        __half2 t0 = __floats2half2_rn(h0, h1);
        __half2 t1 = __floats2half2_rn(h2, h3);
        int kt = nt >> 1, hi = nt & 1;
        A2[kt][2 * hi] = *(unsigned int*)&t0;
        A2[kt][2 * hi + 1] = *(unsigned int*)&t1;
    }

    // ---- MMA2: u2[16 x 32] = hidden[16 x 64] @ Wc[64 x 32-slice] ----
    float d[4][4];
#pragma unroll
    for (int nt = 0; nt < 4; nt++)
#pragma unroll
        for (int q = 0; q < 4; q++) d[nt][q] = 0.f;

    int li8 = lane & 7, seg = lane >> 3;
#pragma unroll
    for (int kt = 0; kt < 4; kt++) {
        int k0 = kt * 16;
        unsigned int bfr[8];
#pragma unroll
        for (int hn = 0; hn < 2; hn++) {
            int n0 = wc + hn * 16;
            unsigned int addr = sptr(&sh_wt[(k0 + li8 + (seg & 1) * 8) * HP + n0 + (seg >> 1) * 8]);
            asm volatile("ldmatrix.sync.aligned.m8n8.x4.trans.shared.b16 {%0,%1,%2,%3}, [%4];"
                         : "=r"(bfr[4 * hn]), "=r"(bfr[4 * hn + 1]),
                           "=r"(bfr[4 * hn + 2]), "=r"(bfr[4 * hn + 3]) : "r"(addr));
        }
#pragma unroll
        for (int nt = 0; nt < 4; nt++) {
            asm volatile(
                "mma.sync.aligned.m16n8k16.row.col.f32.f16.f16.f32 "
                "{%0,%1,%2,%3}, {%4,%5,%6,%7}, {%8,%9}, {%0,%1,%2,%3};"
                : "+f"(d[nt][0]), "+f"(d[nt][1]), "+f"(d[nt][2]), "+f"(d[nt][3])
                : "r"(A2[kt][0]), "r"(A2[kt][1]), "r"(A2[kt][2]), "r"(A2[kt][3]),
                  "r"(bfr[2 * nt]), "r"(bfr[2 * nt + 1]));
        }
    }

    // ---- epilogue-2: scale by dis, pack fp16, store to g_u2h ----
    int cbase = wc + 2 * m;
    unsigned int* u2 = (unsigned int*)g_u2h;
#pragma unroll
    for (int nt = 0; nt < 4; nt++) {
        int c = cbase + nt * 8;
        if (r1 < NN) {
            __half2 h = __floats2half2_rn(d[nt][0] * dv0, d[nt][1] * dv0);
            u2[(size_t)r1 * 32 + (c >> 1)] = *(unsigned int*)&h;
        }
        if (r2 < NN) {
            __half2 h = __floats2half2_rn(d[nt][2] * dv1, d[nt][3] * dv1);
            u2[(size_t)r2 * 32 + (c >> 1)] = *(unsigned int*)&h;
        }
    }
}

// ---------------- branchless padded fp16 gather core --------------------------
#define ACCV(v) { float2 _a = __half22float2(*(__half2*)&(v).x); \
                  float2 _b = __half22float2(*(__half2*)&(v).y); \
                  acc.x += _a.x; acc.y += _a.y; acc.z += _b.x; acc.w += _b.y; }

__device__ __forceinline__ float4 gatherp(const uint2* __restrict__ buf,
                                          const int* __restrict__ sl,
                                          int cntp, int half, int li) {
    float4 acc = make_float4(0.f, 0.f, 0.f, 0.f);
    int k = 0;
    for (; k + 16 <= cntp; k += 16) {
        int s0 = sl[k + half],      s1 = sl[k + half + 2];
        int s2 = sl[k + half + 4],  s3 = sl[k + half + 6];
        int s4 = sl[k + half + 8],  s5 = sl[k + half + 10];
        int s6 = sl[k + half + 12], s7 = sl[k + half + 14];
        uint2 v0 = buf[(size_t)s0 * 16 + li], v1 = buf[(size_t)s1 * 16 + li];
        uint2 v2 = buf[(size_t)s2 * 16 + li], v3 = buf[(size_t)s3 * 16 + li];
        uint2 v4 = buf[(size_t)s4 * 16 + li], v5 = buf[(size_t)s5 * 16 + li];
        uint2 v6 = buf[(size_t)s6 * 16 + li], v7 = buf[(size_t)s7 * 16 + li];
        ACCV(v0); ACCV(v1); ACCV(v2); ACCV(v3);
        ACCV(v4); ACCV(v5); ACCV(v6); ACCV(v7);
    }
    if (k < cntp) {
        int s0 = sl[k + half],     s1 = sl[k + half + 2];
        int s2 = sl[k + half + 4], s3 = sl[k + half + 6];
        uint2 v0 = buf[(size_t)s0 * 16 + li], v1 = buf[(size_t)s1 * 16 + li];
        uint2 v2 = buf[(size_t)s2 * 16 + li], v3 = buf[(size_t)s3 * 16 + li];
        ACCV(v0); ACCV(v1); ACCV(v2); ACCV(v3);
    }
    acc.x += __shfl_xor_sync(FULLMASK, acc.x, 16);
    acc.y += __shfl_xor_sync(FULLMASK, acc.y, 16);
    acc.z += __shfl_xor_sync(FULLMASK, acc.z, 16);
    acc.w += __shfl_xor_sync(FULLMASK, acc.w, 16);
    return acc;
}

// ---------------- fused gather-2 + mu/logvar/z (warp per node) ----------------
__global__ void __launch_bounds__(256) gather2_final_kernel(
    const float* __restrict__ b2, const float* __restrict__ b3,
    const float* __restrict__ eps, float* __restrict__ out) {
    int tid = threadIdx.x, warp = tid >> 5, lane = tid & 31;
    int half = lane >> 4, li = lane & 15;
    int node = blockIdx.x * 8 + warp;

    int craw = g_cnt[node];
    int c = min(craw, CAP);
    int cntp = min((c + 7) & ~7, CAP);
    const int* sl = &g_slot[node * CAP];
    float4 acc = gatherp(g_u2h, sl, cntp, half, li);

    float val[4] = {0.f, 0.f, 0.f, 0.f};
    if (half == 0) {
        uint2 sv = g_u2h[(size_t)node * 16 + li];
        float2 s0 = __half22float2(*(__half2*)&sv.x);
        float2 s1 = __half22float2(*(__half2*)&sv.y);
        float dv = rsqrtf((float)craw + 1.0f);
        int c0 = li * 4;
        const float* bsrc = (c0 < 32) ? &b2[c0] : &b3[c0 - 32];
        float4 bb = *(const float4*)bsrc;
        val[0] = fmaxf((acc.x + s0.x) * dv + bb.x, 0.f);
        val[1] = fmaxf((acc.y + s0.y) * dv + bb.y, 0.f);
        val[2] = fmaxf((acc.z + s1.x) * dv + bb.z, 0.f);
        val[3] = fmaxf((acc.w + s1.y) * dv + bb.w, 0.f);
    }
    float lv0 = __shfl_down_sync(FULLMASK, val[0], 8);
    float lv1 = __shfl_down_sync(FULLMASK, val[1], 8);
    float lv2 = __shfl_down_sync(FULLMASK, val[2], 8);
    float lv3 = __shfl_down_sync(FULLMASK, val[3], 8);

    const int NZ = NN * 32;
    const int NP = GG * DIN;
    if (lane < 8) {
        int t = node * 32 + lane * 4;
        float4 ev = *(const float4*)&eps[t];
        float4 z;
        z.x = ev.x * __expf(lv0) + val[0];
        z.y = ev.y * __expf(lv1) + val[1];
        z.z = ev.z * __expf(lv2) + val[2];
        z.w = ev.w * __expf(lv3) + val[3];
        *(float4*)&out[t] = z;
        *(float4*)&out[NZ + NP + t] = make_float4(val[0], val[1], val[2], val[3]);
    } else if (lane < 16) {
        int t = node * 32 + (lane - 8) * 4;
        *(float4*)&out[2 * NZ + NP + t] = make_float4(val[0], val[1], val[2], val[3]);
    }
}

// ---------------- pooling: warp-uniform fast path -----------------------------
__global__ void __launch_bounds__(256) pool_kernel(const float* __restrict__ x,
                                                   const char* __restrict__ batch,
                                                   const char* __restrict__ ei) {
    int lane = threadIdx.x & 31;
    int probe = ((const int*)ei)[2 * lane + 1];
    bool is64 = (__ballot_sync(FULLMASK, probe != 0) == 0u);
    int gw = (blockIdx.x * 256 + threadIdx.x) >> 5;
    int nw = (gridDim.x * 256) >> 5;
    for (int base = gw * 32; base < NN; base += nw * 32) {  // NN % 32 == 0
        int n = base + lane;
        int b = is64 ? (int)((const long long*)batch)[n] : ((const int*)batch)[n];
        float xv[DIN];
#pragma unroll
        for (int k = 0; k < DIN; k++) xv[k] = x[n * DIN + k];
        int b0 = __shfl_sync(FULLMASK, b, 0);
        if (__all_sync(FULLMASK, b == b0)) {
#pragma unroll
            for (int k = 0; k < DIN; k++)
#pragma unroll
                for (int o = 16; o > 0; o >>= 1)
                    xv[k] += __shfl_xor_sync(FULLMASK, xv[k], o);
            if (lane == 0) {
#pragma unroll
                for (int k = 0; k < DIN; k++) atomicAdd(&g_pool[b0 * 8 + k], xv[k]);
                atomicAdd(&g_pool[b0 * 8 + 7], 32.0f);
            }
        } else {
#pragma unroll
            for (int k = 0; k < DIN; k++) atomicAdd(&g_pool[b * 8 + k], xv[k]);
            atomicAdd(&g_pool[b * 8 + 7], 1.0f);
        }
    }
}

__global__ void poolfin_kernel(float* __restrict__ out) {
    int t = blockIdx.x * blockDim.x + threadIdx.x;
    if (t >= GG * DIN) return;
    int g = t / DIN, k = t % DIN;
    float cnt = g_pool[g * 8 + 7];
    out[NN * 32 + g * DIN + k] = g_pool[g * 8 + k] / fmaxf(cnt, 1.0f);
}

// ---------------- launch -----------------------------------------------------
extern "C" void kernel_launch(void* const* d_in, const int* in_sizes, int n_in,
                              void* d_out, int out_size) {
    const float* x   = (const float*)d_in[0];
    const char*  ei  = (const char*)d_in[1];
    const char*  bat = (const char*)d_in[2];
    const float* W1  = (const float*)d_in[3];
    const float* b1  = (const float*)d_in[4];
    const float* W2  = (const float*)d_in[5];
    const float* b2  = (const float*)d_in[6];
    const float* W3  = (const float*)d_in[7];
    const float* b3  = (const float*)d_in[8];
    const float* eps = (const float*)d_in[9];
    float* out = (float*)d_out;

    // side stream + events for overlapping pooling with the main chain.
    // Created on the FIRST (uncaptured correctness) call; reused during capture.
    static cudaStream_t s_pool = nullptr;
    static cudaEvent_t ev_fork = nullptr, ev_join = nullptr;
    if (s_pool == nullptr) {
        cudaStreamCreate(&s_pool);
        cudaEventCreateWithFlags(&ev_fork, cudaEventDisableTiming);
        cudaEventCreateWithFlags(&ev_join, cudaEventDisableTiming);
    }

    void *p_cnt, *p_pool;
    cudaGetSymbolAddress(&p_cnt, g_cnt);
    cudaGetSymbolAddress(&p_pool, g_pool);

    cudaMemsetAsync(p_cnt, 0, NN * sizeof(int), 0);
    cudaMemsetAsync(p_pool, 0, GG * 8 * sizeof(float), 0);

    // fork: pooling path runs concurrently with the GCN chain
    cudaEventRecord(ev_fork, 0);
    cudaStreamWaitEvent(s_pool, ev_fork, 0);
    pool_kernel<<<128, 256, 0, s_pool>>>(x, bat, ei);
    poolfin_kernel<<<1, 512, 0, s_pool>>>(out);
    cudaEventRecord(ev_join, s_pool);

    fill_kernel<<<(EE / 4 + 255) / 256, 256>>>(ei);
    xs_kernel<<<(NN + 1 + 255) / 256, 256>>>(x);
    gather1_kernel<<<NN / 32, 256>>>();
    hidden_gemm_kernel<<<(NN + 63) / 64, 256>>>(W1, b1, W2, W3);
    gather2_final_kernel<<<NN / 8, 256>>>(b2, b3, eps, out);

    // join
    cudaStreamWaitEvent(0, ev_join, 0);
}

// round 17
// speedup vs baseline: 1.2244x; 1.0003x over previous
#include <cuda_runtime.h>
#include <cuda_bf16.h>
#include <cuda_fp16.h>
#include <math.h>

#define NN 100000
#define EE 1600000
#define DIN 7
#define GG 64
#define CAP 96
#define HP 72          // half pitch for mma smem tiles (144B, conflict-free ldmatrix)
#define FULLMASK 0xffffffffu

// ---------------- scratch (device globals; no allocation allowed) -------------
__device__ uint4  g_xsh[NN + 1];        // x*dis as 8 fp16 (7 real + 0 pad); row NN = 0
__device__ uint2  g_u2h[(NN + 1) * 16]; // (hidden1 @ [W2|W3]) * dis (fp16); row NN = 0
__device__ int    g_slot[NN * CAP];     // per-dst src lists (padded to mult of 8)
__device__ int    g_cnt[NN];            // in-degree
__device__ float  g_pool[GG * 8];

__device__ __forceinline__ unsigned int sptr(const void* p) {
    return (unsigned int)__cvta_generic_to_shared(p);
}

// ---------------- CSR fill: 4 edges/thread, per-warp dtype detect -------------
__global__ void __launch_bounds__(256) fill_kernel(const char* __restrict__ ei) {
    int lane = threadIdx.x & 31;
    int probe = ((const int*)ei)[2 * lane + 1];
    bool is64 = (__ballot_sync(FULLMASK, probe != 0) == 0u);
    int t = blockIdx.x * 256 + threadIdx.x;
    if (t >= EE / 4) return;
    int s[4], d[4];
    if (is64) {
        const longlong2* sp = (const longlong2*)ei;
        const longlong2* dp = (const longlong2*)(ei + 8LL * EE);
        longlong2 a = sp[2 * t], b = sp[2 * t + 1];
        longlong2 c = dp[2 * t], e = dp[2 * t + 1];
        s[0] = (int)a.x; s[1] = (int)a.y; s[2] = (int)b.x; s[3] = (int)b.y;
        d[0] = (int)c.x; d[1] = (int)c.y; d[2] = (int)e.x; d[3] = (int)e.y;
    } else {
        int4 a = ((const int4*)ei)[t];
        int4 c = ((const int4*)(ei + 4LL * EE))[t];
        s[0] = a.x; s[1] = a.y; s[2] = a.z; s[3] = a.w;
        d[0] = c.x; d[1] = c.y; d[2] = c.z; d[3] = c.w;
    }
#pragma unroll
    for (int j = 0; j < 4; j++) {
        int pos = atomicAdd(&g_cnt[d[j]], 1);
        if (pos < CAP) g_slot[d[j] * CAP + pos] = s[j];
    }
}

// ---------------- xs = fp16[x*dis, 0] (coalesced staging); pad slots ----------
__global__ void __launch_bounds__(256) xs_kernel(const float* __restrict__ x) {
    __shared__ float sx[256 * DIN];
    int tid = threadIdx.x;
    int nb = blockIdx.x * 256;
    long long base = (long long)nb * DIN;
    const long long XTOT = (long long)NN * DIN;
    for (int i = tid; i < 256 * DIN; i += 256) {
        long long g = base + i;
        sx[i] = (g < XTOT) ? x[g] : 0.f;
    }
    __syncthreads();
    int n = nb + tid;
    if (n > NN) return;
    if (n == NN) {
        g_xsh[NN] = make_uint4(0u, 0u, 0u, 0u);
        uint2 z = make_uint2(0u, 0u);
#pragma unroll
        for (int i = 0; i < 16; i++) g_u2h[NN * 16 + i] = z;
        return;
    }
    int craw = g_cnt[n];
    float dv = rsqrtf((float)craw + 1.0f);
    const float* xr = &sx[tid * DIN];
    __half2 h0 = __floats2half2_rn(xr[0] * dv, xr[1] * dv);
    __half2 h1 = __floats2half2_rn(xr[2] * dv, xr[3] * dv);
    __half2 h2 = __floats2half2_rn(xr[4] * dv, xr[5] * dv);
    __half2 h3 = __floats2half2_rn(xr[6] * dv, 0.f);
    uint4 v;
    v.x = *(unsigned int*)&h0;
    v.y = *(unsigned int*)&h1;
    v.z = *(unsigned int*)&h2;
    v.w = *(unsigned int*)&h3;
    g_xsh[n] = v;
    int c = min(craw, CAP);
    int cp = min((c + 7) & ~7, CAP);
    for (int k = c; k < cp; k++) g_slot[n * CAP + k] = NN;
}

// ---------------- fused gather-1 + MMA-chained hidden/GEMM -> u2 fp16 ---------
// 64 nodes/block. Phase 1: gather xs into sh_pre (2 rounds, 8 lanes/node).
// Phase 2 (after ONE barrier): pre@W1 via m16n8k8, relu/bias/dis in D-frags,
// repack to A-frags, m16n8k16 against Wc, store u2 fp16.
__global__ void __launch_bounds__(256) gather_hidden_kernel(
    const float* __restrict__ W1, const float* __restrict__ b1,
    const float* __restrict__ W2, const float* __restrict__ W3) {
    __shared__ __half sh_wt[64 * HP];        // Wc, row-major [k][64]
    __shared__ unsigned int sh_w1h[64 * 4];  // packed W1 B-fragments
    __shared__ float sh_b1[64];
    __shared__ float sh_pre[64 * 8];
    __shared__ float sh_dis[64];
    int tid = threadIdx.x;
    int nb = blockIdx.x * 64;
    int warp = tid >> 5, lane = tid & 31;

    // ---- stage weights (overlaps with gather loads below via MLP) ----
    for (int i = tid; i < 2048; i += 256) {          // 2048 half2 pairs
        int k = i >> 5, jp = i & 31;                 // j = 2*jp
        float2 wv = (jp < 16) ? *(const float2*)&W2[k * 32 + 2 * jp]
                              : *(const float2*)&W3[k * 32 + (2 * jp - 32)];
        __half2 h = __floats2half2_rn(wv.x, wv.y);
        *(__half2*)&sh_wt[k * HP + 2 * jp] = h;
    }
    {
        int n = tid >> 2, mm = tid & 3;
        float lo = W1[2 * mm * 64 + n];
        float hi = (mm == 3) ? 0.f : W1[(2 * mm + 1) * 64 + n];
        __half2 h = __floats2half2_rn(lo, hi);
        sh_w1h[tid] = *(unsigned int*)&h;
    }
    if (tid < 64) sh_b1[tid] = b1[tid];

    // ---- phase 1: gather (8 lanes per node, 4 nodes/warp, 2 rounds) ----
    int grp = lane >> 3, el = lane & 7;
#pragma unroll
    for (int r = 0; r < 2; r++) {
        int ln = r * 32 + warp * 4 + grp;
        int node = nb + ln;
        float4 a0 = make_float4(0.f, 0.f, 0.f, 0.f);
        float4 a1 = make_float4(0.f, 0.f, 0.f, 0.f);
        float dv = 0.f;
        uint4 sv = make_uint4(0u, 0u, 0u, 0u);
        if (node < NN) {
            int craw = g_cnt[node];
            dv = rsqrtf((float)craw + 1.0f);
            int c = min(craw, CAP);
            int cntp = min((c + 7) & ~7, CAP);
            const int* sl = &g_slot[node * CAP];
            for (int base = 0; base < cntp; base += 8) {
                uint4 v = g_xsh[sl[base + el]];    // padded with NN (zero row)
                float2 p0 = __half22float2(*(__half2*)&v.x);
                float2 p1 = __half22float2(*(__half2*)&v.y);
                float2 p2 = __half22float2(*(__half2*)&v.z);
                float2 p3 = __half22float2(*(__half2*)&v.w);
                a0.x += p0.x; a0.y += p0.y; a0.z += p1.x; a0.w += p1.y;
                a1.x += p2.x; a1.y += p2.y; a1.z += p3.x; a1.w += p3.y;
            }
            sv = g_xsh[node];
        }
#pragma unroll
        for (int off = 1; off <= 4; off <<= 1) {
            a0.x += __shfl_xor_sync(FULLMASK, a0.x, off);
            a0.y += __shfl_xor_sync(FULLMASK, a0.y, off);
            a0.z += __shfl_xor_sync(FULLMASK, a0.z, off);
            a0.w += __shfl_xor_sync(FULLMASK, a0.w, off);
            a1.x += __shfl_xor_sync(FULLMASK, a1.x, off);
            a1.y += __shfl_xor_sync(FULLMASK, a1.y, off);
            a1.z += __shfl_xor_sync(FULLMASK, a1.z, off);
            a1.w += __shfl_xor_sync(FULLMASK, a1.w, off);
        }
        if (el == 0) {
            float2 p0 = __half22float2(*(__half2*)&sv.x);
            float2 p1 = __half22float2(*(__half2*)&sv.y);
            *(float4*)&sh_pre[ln * 8] =
                make_float4(a0.x + p0.x, a0.y + p0.y, a0.z + p1.x, a0.w + p1.y);
            sh_dis[ln] = dv;
        } else if (el == 4) {
            float2 p2 = __half22float2(*(__half2*)&sv.z);
            float2 p3 = __half22float2(*(__half2*)&sv.w);
            *(float4*)&sh_pre[ln * 8 + 4] =
                make_float4(a1.x + p2.x, a1.y + p2.y, a1.z + p3.x, a1.w + p3.y);
        }
    }
    __syncthreads();

    // ---- phase 2: MMA chain ----
    int wr = (warp >> 1) << 4, wc = (warp & 1) << 5;
    int gr = lane >> 2, m = lane & 3;
    int l1 = wr + gr, l2 = l1 + 8;
    int r1 = nb + l1, r2 = nb + l2;
    float2 pA = *(const float2*)&sh_pre[l1 * 8 + 2 * m];
    float2 pB = *(const float2*)&sh_pre[l2 * 8 + 2 * m];
    float dv0 = sh_dis[l1], dv1 = sh_dis[l2];

    __half2 a0h = __floats2half2_rn(pA.x, pA.y);
    __half2 a1h = __floats2half2_rn(pB.x, pB.y);
    unsigned int A0 = *(unsigned int*)&a0h;
    unsigned int A1 = *(unsigned int*)&a1h;

    float d1[8][4];
#pragma unroll
    for (int nt = 0; nt < 8; nt++) {
        d1[nt][0] = 0.f; d1[nt][1] = 0.f; d1[nt][2] = 0.f; d1[nt][3] = 0.f;
        unsigned int bw = sh_w1h[lane + 32 * nt];
        asm volatile(
            "mma.sync.aligned.m16n8k8.row.col.f32.f16.f16.f32 "
            "{%0,%1,%2,%3}, {%4,%5}, {%6}, {%0,%1,%2,%3};"
            : "+f"(d1[nt][0]), "+f"(d1[nt][1]), "+f"(d1[nt][2]), "+f"(d1[nt][3])
            : "r"(A0), "r"(A1), "r"(bw));
    }

    unsigned int A2[4][4];
#pragma unroll
    for (int nt = 0; nt < 8; nt++) {
        float2 bb = *(const float2*)&sh_b1[8 * nt + 2 * m];
        float h0 = fmaxf(dv0 * d1[nt][0] + bb.x, 0.f);
        float h1 = fmaxf(dv0 * d1[nt][1] + bb.y, 0.f);
        float h2 = fmaxf(dv1 * d1[nt][2] + bb.x, 0.f);
        float h3 = fmaxf(dv1 * d1[nt][3] + bb.y, 0.f);
        __half2 t0 = __floats2half2_rn(h0, h1);
        __half2 t1 = __floats2half2_rn(h2, h3);
        int kt = nt >> 1, hi = nt & 1;
        A2[kt][2 * hi] = *(unsigned int*)&t0;
        A2[kt][2 * hi + 1] = *(unsigned int*)&t1;
    }

    float d[4][4];
#pragma unroll
    for (int nt = 0; nt < 4; nt++)
#pragma unroll
        for (int q = 0; q < 4; q++) d[nt][q] = 0.f;

    int li8 = lane & 7, seg = lane >> 3;
#pragma unroll
    for (int kt = 0; kt < 4; kt++) {
        int k0 = kt * 16;
        unsigned int bfr[8];
#pragma unroll
        for (int hn = 0; hn < 2; hn++) {
            int n0 = wc + hn * 16;
            unsigned int addr = sptr(&sh_wt[(k0 + li8 + (seg & 1) * 8) * HP + n0 + (seg >> 1) * 8]);
            asm volatile("ldmatrix.sync.aligned.m8n8.x4.trans.shared.b16 {%0,%1,%2,%3}, [%4];"
                         : "=r"(bfr[4 * hn]), "=r"(bfr[4 * hn + 1]),
                           "=r"(bfr[4 * hn + 2]), "=r"(bfr[4 * hn + 3]) : "r"(addr));
        }
#pragma unroll
        for (int nt = 0; nt < 4; nt++) {
            asm volatile(
                "mma.sync.aligned.m16n8k16.row.col.f32.f16.f16.f32 "
                "{%0,%1,%2,%3}, {%4,%5,%6,%7}, {%8,%9}, {%0,%1,%2,%3};"
                : "+f"(d[nt][0]), "+f"(d[nt][1]), "+f"(d[nt][2]), "+f"(d[nt][3])
                : "r"(A2[kt][0]), "r"(A2[kt][1]), "r"(A2[kt][2]), "r"(A2[kt][3]),
                  "r"(bfr[2 * nt]), "r"(bfr[2 * nt + 1]));
        }
    }

    int cbase = wc + 2 * m;
    unsigned int* u2 = (unsigned int*)g_u2h;
#pragma unroll
    for (int nt = 0; nt < 4; nt++) {
        int c = cbase + nt * 8;
        if (r1 < NN) {
            __half2 h = __floats2half2_rn(d[nt][0] * dv0, d[nt][1] * dv0);
            u2[(size_t)r1 * 32 + (c >> 1)] = *(unsigned int*)&h;
        }
        if (r2 < NN) {
            __half2 h = __floats2half2_rn(d[nt][2] * dv1, d[nt][3] * dv1);
            u2[(size_t)r2 * 32 + (c >> 1)] = *(unsigned int*)&h;
        }
    }
}

// ---------------- branchless padded fp16 gather core --------------------------
#define ACCV(v) { float2 _a = __half22float2(*(__half2*)&(v).x); \
                  float2 _b = __half22float2(*(__half2*)&(v).y); \
                  acc.x += _a.x; acc.y += _a.y; acc.z += _b.x; acc.w += _b.y; }

__device__ __forceinline__ float4 gatherp(const uint2* __restrict__ buf,
                                          const int* __restrict__ sl,
                                          int cntp, int half, int li) {
    float4 acc = make_float4(0.f, 0.f, 0.f, 0.f);
    int k = 0;
    for (; k + 16 <= cntp; k += 16) {
        int s0 = sl[k + half],      s1 = sl[k + half + 2];
        int s2 = sl[k + half + 4],  s3 = sl[k + half + 6];
        int s4 = sl[k + half + 8],  s5 = sl[k + half + 10];
        int s6 = sl[k + half + 12], s7 = sl[k + half + 14];
        uint2 v0 = buf[(size_t)s0 * 16 + li], v1 = buf[(size_t)s1 * 16 + li];
        uint2 v2 = buf[(size_t)s2 * 16 + li], v3 = buf[(size_t)s3 * 16 + li];
        uint2 v4 = buf[(size_t)s4 * 16 + li], v5 = buf[(size_t)s5 * 16 + li];
        uint2 v6 = buf[(size_t)s6 * 16 + li], v7 = buf[(size_t)s7 * 16 + li];
        ACCV(v0); ACCV(v1); ACCV(v2); ACCV(v3);
        ACCV(v4); ACCV(v5); ACCV(v6); ACCV(v7);
    }
    if (k < cntp) {
        int s0 = sl[k + half],     s1 = sl[k + half + 2];
        int s2 = sl[k + half + 4], s3 = sl[k + half + 6];
        uint2 v0 = buf[(size_t)s0 * 16 + li], v1 = buf[(size_t)s1 * 16 + li];
        uint2 v2 = buf[(size_t)s2 * 16 + li], v3 = buf[(size_t)s3 * 16 + li];
        ACCV(v0); ACCV(v1); ACCV(v2); ACCV(v3);
    }
    acc.x += __shfl_xor_sync(FULLMASK, acc.x, 16);
    acc.y += __shfl_xor_sync(FULLMASK, acc.y, 16);
    acc.z += __shfl_xor_sync(FULLMASK, acc.z, 16);
    acc.w += __shfl_xor_sync(FULLMASK, acc.w, 16);
    return acc;
}

// ---------------- fused gather-2 + mu/logvar/z (warp per node) ----------------
__global__ void __launch_bounds__(256) gather2_final_kernel(
    const float* __restrict__ b2, const float* __restrict__ b3,
    const float* __restrict__ eps, float* __restrict__ out) {
    int tid = threadIdx.x, warp = tid >> 5, lane = tid & 31;
    int half = lane >> 4, li = lane & 15;
    int node = blockIdx.x * 8 + warp;

    int craw = g_cnt[node];
    int c = min(craw, CAP);
    int cntp = min((c + 7) & ~7, CAP);
    const int* sl = &g_slot[node * CAP];
    float4 acc = gatherp(g_u2h, sl, cntp, half, li);

    float val[4] = {0.f, 0.f, 0.f, 0.f};
    if (half == 0) {
        uint2 sv = g_u2h[(size_t)node * 16 + li];
        float2 s0 = __half22float2(*(__half2*)&sv.x);
        float2 s1 = __half22float2(*(__half2*)&sv.y);
        float dv = rsqrtf((float)craw + 1.0f);
        int c0 = li * 4;
        const float* bsrc = (c0 < 32) ? &b2[c0] : &b3[c0 - 32];
        float4 bb = *(const float4*)bsrc;
        val[0] = fmaxf((acc.x + s0.x) * dv + bb.x, 0.f);
        val[1] = fmaxf((acc.y + s0.y) * dv + bb.y, 0.f);
        val[2] = fmaxf((acc.z + s1.x) * dv + bb.z, 0.f);
        val[3] = fmaxf((acc.w + s1.y) * dv + bb.w, 0.f);
    }
    float lv0 = __shfl_down_sync(FULLMASK, val[0], 8);
    float lv1 = __shfl_down_sync(FULLMASK, val[1], 8);
    float lv2 = __shfl_down_sync(FULLMASK, val[2], 8);
    float lv3 = __shfl_down_sync(FULLMASK, val[3], 8);

    const int NZ = NN * 32;
    const int NP = GG * DIN;
    if (lane < 8) {
        int t = node * 32 + lane * 4;
        float4 ev = *(const float4*)&eps[t];
        float4 z;
        z.x = ev.x * __expf(lv0) + val[0];
        z.y = ev.y * __expf(lv1) + val[1];
        z.z = ev.z * __expf(lv2) + val[2];
        z.w = ev.w * __expf(lv3) + val[3];
        *(float4*)&out[t] = z;
        *(float4*)&out[NZ + NP + t] = make_float4(val[0], val[1], val[2], val[3]);
    } else if (lane < 16) {
        int t = node * 32 + (lane - 8) * 4;
        *(float4*)&out[2 * NZ + NP + t] = make_float4(val[0], val[1], val[2], val[3]);
    }
}

// ---------------- pooling: warp-uniform fast path -----------------------------
__global__ void __launch_bounds__(256) pool_kernel(const float* __restrict__ x,
                                                   const char* __restrict__ batch,
                                                   const char* __restrict__ ei) {
    int lane = threadIdx.x & 31;
    int probe = ((const int*)ei)[2 * lane + 1];
    bool is64 = (__ballot_sync(FULLMASK, probe != 0) == 0u);
    int gw = (blockIdx.x * 256 + threadIdx.x) >> 5;
    int nw = (gridDim.x * 256) >> 5;
    for (int base = gw * 32; base < NN; base += nw * 32) {  // NN % 32 == 0
        int n = base + lane;
        int b = is64 ? (int)((const long long*)batch)[n] : ((const int*)batch)[n];
        float xv[DIN];
#pragma unroll
        for (int k = 0; k < DIN; k++) xv[k] = x[n * DIN + k];
        int b0 = __shfl_sync(FULLMASK, b, 0);
        if (__all_sync(FULLMASK, b == b0)) {
#pragma unroll
            for (int k = 0; k < DIN; k++)
#pragma unroll
                for (int o = 16; o > 0; o >>= 1)
                    xv[k] += __shfl_xor_sync(FULLMASK, xv[k], o);
            if (lane == 0) {
#pragma unroll
                for (int k = 0; k < DIN; k++) atomicAdd(&g_pool[b0 * 8 + k], xv[k]);
                atomicAdd(&g_pool[b0 * 8 + 7], 32.0f);
            }
        } else {
#pragma unroll
            for (int k = 0; k < DIN; k++) atomicAdd(&g_pool[b * 8 + k], xv[k]);
            atomicAdd(&g_pool[b * 8 + 7], 1.0f);
        }
    }
}

__global__ void poolfin_kernel(float* __restrict__ out) {
    int t = blockIdx.x * blockDim.x + threadIdx.x;
    if (t >= GG * DIN) return;
    int g = t / DIN, k = t % DIN;
    float cnt = g_pool[g * 8 + 7];
    out[NN * 32 + g * DIN + k] = g_pool[g * 8 + k] / fmaxf(cnt, 1.0f);
}

// ---------------- launch -----------------------------------------------------
extern "C" void kernel_launch(void* const* d_in, const int* in_sizes, int n_in,
                              void* d_out, int out_size) {
    const float* x   = (const float*)d_in[0];
    const char*  ei  = (const char*)d_in[1];
    const char*  bat = (const char*)d_in[2];
    const float* W1  = (const float*)d_in[3];
    const float* b1  = (const float*)d_in[4];
    const float* W2  = (const float*)d_in[5];
    const float* b2  = (const float*)d_in[6];
    const float* W3  = (const float*)d_in[7];
    const float* b3  = (const float*)d_in[8];
    const float* eps = (const float*)d_in[9];
    float* out = (float*)d_out;

    // side stream + events for overlapping pooling with the main chain.
    // Created on the FIRST (uncaptured correctness) call; reused during capture.
    static cudaStream_t s_pool = nullptr;
    static cudaEvent_t ev_fork = nullptr, ev_join = nullptr;
    if (s_pool == nullptr) {
        cudaStreamCreate(&s_pool);
        cudaEventCreateWithFlags(&ev_fork, cudaEventDisableTiming);
        cudaEventCreateWithFlags(&ev_join, cudaEventDisableTiming);
    }

    void *p_cnt, *p_pool;
    cudaGetSymbolAddress(&p_cnt, g_cnt);
    cudaGetSymbolAddress(&p_pool, g_pool);

    cudaMemsetAsync(p_cnt, 0, NN * sizeof(int), 0);

    // fork: pooling path (memset + pool + poolfin) runs on the side stream
    cudaEventRecord(ev_fork, 0);
    cudaStreamWaitEvent(s_pool, ev_fork, 0);
    cudaMemsetAsync(p_pool, 0, GG * 8 * sizeof(float), s_pool);
    pool_kernel<<<128, 256, 0, s_pool>>>(x, bat, ei);
    poolfin_kernel<<<1, 512, 0, s_pool>>>(out);
    cudaEventRecord(ev_join, s_pool);

    fill_kernel<<<(EE / 4 + 255) / 256, 256>>>(ei);
    xs_kernel<<<(NN + 1 + 255) / 256, 256>>>(x);
    gather_hidden_kernel<<<(NN + 63) / 64, 256>>>(W1, b1, W2, W3);
    gather2_final_kernel<<<NN / 8, 256>>>(b2, b3, eps, out);

    // join
    cudaStreamWaitEvent(0, ev_join, 0);
}